// round 13
// baseline (speedup 1.0000x reference)
#include <cuda_runtime.h>
#include <cstdint>

#define EPSF 1e-6f

#define NP     1024
#define DIM    768
#define QK_LD  6144   /* q|k combined columns: 2 * 48 * 64 */
#define V_LD   3072

typedef unsigned long long u64;

// Packed f32x2 helpers (attention kernel)
#define FFMA2(d, a, b) \
    asm volatile("fma.rn.f32x2 %0, %1, %2, %0;" : "+l"(d) : "l"(a), "l"(b))
#define DUP2(d, s) \
    asm("mov.b64 %0, {%1, %1};" : "=l"(d) : "r"(__float_as_uint(s)))
#define UNPK2(lo, hi, d) \
    asm("mov.b64 {%0, %1}, %2;" : "=f"(lo), "=f"(hi) : "l"(d))

// tf32 split: x ~= hi + lo, both tf32-representable (3xTF32 trick)
__device__ __forceinline__ void tf32_split(float f, float& hi, float& lo) {
    uint32_t h, l;
    asm("cvt.rna.tf32.f32 %0, %1;" : "=r"(h) : "f"(f));
    float r = f - __uint_as_float(h);
    asm("cvt.rna.tf32.f32 %0, %1;" : "=r"(l) : "f"(r));
    hi = __uint_as_float(h);
    lo = __uint_as_float(l);
}

#define MMA_TF32(cc, a, b) \
    asm volatile("mma.sync.aligned.m16n8k8.row.col.f32.tf32.tf32.f32 " \
        "{%0,%1,%2,%3}, {%4,%5,%6,%7}, {%8,%9}, {%0,%1,%2,%3};" \
        : "+f"(cc[0]), "+f"(cc[1]), "+f"(cc[2]), "+f"(cc[3]) \
        : "r"(a[0]), "r"(a[1]), "r"(a[2]), "r"(a[3]), "r"(b[0]), "r"(b[1]))

__device__ __forceinline__ uint32_t smem_u32(const void* p) {
    return (uint32_t)__cvta_generic_to_shared(p);
}
#define CP16(dst, src) \
    asm volatile("cp.async.cg.shared.global [%0], [%1], 16;" :: "r"(dst), "l"(src))
#define CP_COMMIT() asm volatile("cp.async.commit_group;" ::: "memory")
#define CP_WAIT1()  asm volatile("cp.async.wait_group 1;" ::: "memory")

// Scratch (device globals: allowed; no runtime allocation)
__device__ float g_xh [4*NP*DIM],  g_xl [4*NP*DIM];     // x split
__device__ float g_wqh[DIM*3*DIM], g_wql[DIM*3*DIM];    // W_qkv split
__device__ float g_woh[DIM*DIM],   g_wol[DIM*DIM];      // W_out split
__device__ float g_mh [NP*NP],     g_ml [NP*NP];        // mask split
__device__ float g_qkh[NP*QK_LD],  g_qkl[NP*QK_LD];     // feature-mapped q|k, split
__device__ float g_v  [NP*V_LD];                        // v, plain
__device__ float g_qk2[NP*QK_LD];                       // q|k after graph mix, plain
__device__ float g_ath[4*NP*DIM],  g_atl[4*NP*DIM];     // attention out, split

// ---------------------------------------------------------------------------
// Elementwise tf32 pre-split (vectorized)
// ---------------------------------------------------------------------------
__global__ void split_kernel(const float* __restrict__ in,
                             float* __restrict__ hi, float* __restrict__ lo,
                             int n4)
{
    int i = blockIdx.x * blockDim.x + threadIdx.x;
    if (i < n4) {
        float4 v = ((const float4*)in)[i];
        float4 h, l;
        tf32_split(v.x, h.x, l.x);
        tf32_split(v.y, h.y, l.y);
        tf32_split(v.z, h.z, l.z);
        tf32_split(v.w, h.w, l.w);
        ((float4*)hi)[i] = h;
        ((float4*)lo)[i] = l;
    }
}

// ---------------------------------------------------------------------------
// Tensor-core GEMM: 128x128 block tile, 8 warps (4m x 2n), warp tile 32x64,
// K-stage 16, mma.m16n8k8.tf32, 3xTF32, pre-split operands, cp.async
// 3-stage pipeline (no CVT / register staging in mainloop).
// TRANSA=false: A row-major [M,K].  TRANSA=true: op(A)=A^T with A [K,M].
// EPI 0: qkv relu/eps + split scatter   EPI 1: C = (hi+lo) + 0.1*acc
// EPI 2: C = acc + bias
// ---------------------------------------------------------------------------
#define SMEM_T   (3 * 8704 * 4)    /* TRANSA  stage = 4*16*136 floats */
#define SMEM_NT  (3 * 9472 * 4)    /* !TRANSA stage = 2*128*20 + 2*16*136 */

template<bool TRANSA, int EPI>
__global__ __launch_bounds__(256, 1)
void tgemm_kernel(const float* __restrict__ Ah_g, const float* __restrict__ Al_g,
                  const float* __restrict__ Bh_g, const float* __restrict__ Bl_g,
                  float* __restrict__ C, const float* __restrict__ bias,
                  int M, int N, int K, int lda, int ldb)
{
    constexpr int AL_OFF = TRANSA ? 2176 : 2560;   // floats
    constexpr int BH_OFF = TRANSA ? 4352 : 5120;
    constexpr int BL_OFF = BH_OFF + 2176;
    constexpr int STAGE  = BL_OFF + 2176;

    extern __shared__ float sm_[];

    const int tid  = threadIdx.x;
    const int lane = tid & 31;
    const int warp = tid >> 5;
    const int wm   = warp & 3;
    const int wn   = warp >> 2;
    const int g    = lane >> 2;
    const int tg   = lane & 3;
    const int m_base = blockIdx.y * 128;
    const int n_base = blockIdx.x * 128;

    // per-thread cp.async coordinates (fixed across k-tiles)
    const int ar = TRANSA ? (tid >> 4) : (tid >> 1);
    const int ac = TRANSA ? ((tid & 15) * 8) : ((tid & 1) * 8);
    const int br = tid >> 4;
    const int bc = (tid & 15) * 8;

    const int nk = K >> 4;

    auto issue = [&](int kt) {
        if (kt < nk) {
            float* base = sm_ + (kt % 3) * STAGE;
            const int k0 = kt << 4;
            const float *sAh, *sAl;
            uint32_t dAh, dAl;
            if (TRANSA) {
                sAh = &Ah_g[(size_t)(k0 + ar) * lda + m_base + ac];
                sAl = &Al_g[(size_t)(k0 + ar) * lda + m_base + ac];
                dAh = smem_u32(&base[ar * 136 + ac]);
                dAl = smem_u32(&base[AL_OFF + ar * 136 + ac]);
            } else {
                sAh = &Ah_g[(size_t)(m_base + ar) * lda + k0 + ac];
                sAl = &Al_g[(size_t)(m_base + ar) * lda + k0 + ac];
                dAh = smem_u32(&base[ar * 20 + ac]);
                dAl = smem_u32(&base[AL_OFF + ar * 20 + ac]);
            }
            CP16(dAh, sAh); CP16(dAh + 16, sAh + 4);
            CP16(dAl, sAl); CP16(dAl + 16, sAl + 4);
            const float* sBh = &Bh_g[(size_t)(k0 + br) * ldb + n_base + bc];
            const float* sBl = &Bl_g[(size_t)(k0 + br) * ldb + n_base + bc];
            uint32_t dBh = smem_u32(&base[BH_OFF + br * 136 + bc]);
            uint32_t dBl = smem_u32(&base[BL_OFF + br * 136 + bc]);
            CP16(dBh, sBh); CP16(dBh + 16, sBh + 4);
            CP16(dBl, sBl); CP16(dBl + 16, sBl + 4);
        }
        CP_COMMIT();
    };

    float c[2][8][4];
    #pragma unroll
    for (int mt = 0; mt < 2; mt++)
        #pragma unroll
        for (int nt = 0; nt < 8; nt++)
            #pragma unroll
            for (int q = 0; q < 4; q++) c[mt][nt][q] = 0.f;

    issue(0);
    issue(1);

    for (int kt = 0; kt < nk; kt++) {
        CP_WAIT1();                     // this thread's stage-kt copies done
        __syncthreads();                // visible to all; stage (kt+2)%3 free
        issue(kt + 2);                  // next-next tile flies during MMAs

        const float* base = sm_ + (kt % 3) * STAGE;
        const float* Ah = base;
        const float* Al = base + AL_OFF;
        const float* Bh = base + BH_OFF;
        const float* Bl = base + BL_OFF;

        #pragma unroll
        for (int ks = 0; ks < 16; ks += 8) {
            uint32_t bh[8][2], bl[8][2];
            #pragma unroll
            for (int nt = 0; nt < 8; nt++) {
                const int cb = wn * 64 + nt * 8 + g;
                bh[nt][0] = __float_as_uint(Bh[(ks + tg) * 136 + cb]);
                bh[nt][1] = __float_as_uint(Bh[(ks + tg + 4) * 136 + cb]);
                bl[nt][0] = __float_as_uint(Bl[(ks + tg) * 136 + cb]);
                bl[nt][1] = __float_as_uint(Bl[(ks + tg + 4) * 136 + cb]);
            }
            #pragma unroll
            for (int mt = 0; mt < 2; mt++) {
                const int rb = wm * 32 + mt * 16;
                uint32_t ah[4], al[4];
                if (TRANSA) {
                    ah[0] = __float_as_uint(Ah[(ks + tg) * 136 + rb + g]);
                    ah[1] = __float_as_uint(Ah[(ks + tg) * 136 + rb + g + 8]);
                    ah[2] = __float_as_uint(Ah[(ks + tg + 4) * 136 + rb + g]);
                    ah[3] = __float_as_uint(Ah[(ks + tg + 4) * 136 + rb + g + 8]);
                    al[0] = __float_as_uint(Al[(ks + tg) * 136 + rb + g]);
                    al[1] = __float_as_uint(Al[(ks + tg) * 136 + rb + g + 8]);
                    al[2] = __float_as_uint(Al[(ks + tg + 4) * 136 + rb + g]);
                    al[3] = __float_as_uint(Al[(ks + tg + 4) * 136 + rb + g + 8]);
                } else {
                    ah[0] = __float_as_uint(Ah[(rb + g) * 20 + ks + tg]);
                    ah[1] = __float_as_uint(Ah[(rb + g + 8) * 20 + ks + tg]);
                    ah[2] = __float_as_uint(Ah[(rb + g) * 20 + ks + tg + 4]);
                    ah[3] = __float_as_uint(Ah[(rb + g + 8) * 20 + ks + tg + 4]);
                    al[0] = __float_as_uint(Al[(rb + g) * 20 + ks + tg]);
                    al[1] = __float_as_uint(Al[(rb + g + 8) * 20 + ks + tg]);
                    al[2] = __float_as_uint(Al[(rb + g) * 20 + ks + tg + 4]);
                    al[3] = __float_as_uint(Al[(rb + g + 8) * 20 + ks + tg + 4]);
                }
                #pragma unroll
                for (int nt = 0; nt < 8; nt++) {
                    MMA_TF32(c[mt][nt], ah, bh[nt]);   // hi*hi
                    MMA_TF32(c[mt][nt], ah, bl[nt]);   // hi*lo
                    MMA_TF32(c[mt][nt], al, bh[nt]);   // lo*hi
                }
            }
        }
    }

    // -------- epilogue (per-thread: rows r and r+8, col pair 2tg,2tg+1) -----
    #pragma unroll
    for (int mt = 0; mt < 2; mt++) {
        #pragma unroll
        for (int nt = 0; nt < 8; nt++) {
            const int row0 = m_base + wm * 32 + mt * 16 + g;
            const int col  = n_base + wn * 64 + nt * 8 + 2 * tg;
            #pragma unroll
            for (int h2 = 0; h2 < 2; h2++) {
                const int row = row0 + h2 * 8;
                float vx = c[mt][nt][h2 * 2 + 0];
                float vy = c[mt][nt][h2 * 2 + 1];
                if (EPI == 0) {
                    const int bb = row >> 10;
                    const int n  = row & 1023;
                    if (col < 1536) {
                        vx = fmaxf(vx, 0.f) + EPSF;
                        vy = fmaxf(vy, 0.f) + EPSF;
                        float hx, lx, hy, ly;
                        tf32_split(vx, hx, lx);
                        tf32_split(vy, hy, ly);
                        const int off = (col < 768) ? (bb * 768 + col)
                                                    : (3072 + bb * 768 + (col - 768));
                        *(float2*)&g_qkh[(size_t)n * QK_LD + off] = make_float2(hx, hy);
                        *(float2*)&g_qkl[(size_t)n * QK_LD + off] = make_float2(lx, ly);
                    } else {
                        *(float2*)&g_v[(size_t)n * V_LD + bb * 768 + (col - 1536)] =
                            make_float2(vx, vy);
                    }
                } else if (EPI == 1) {
                    float2 fh = *(const float2*)&g_qkh[(size_t)row * N + col];
                    float2 fl = *(const float2*)&g_qkl[(size_t)row * N + col];
                    *(float2*)&C[(size_t)row * N + col] =
                        make_float2((fh.x + fl.x) + 0.1f * vx,
                                    (fh.y + fl.y) + 0.1f * vy);
                } else {
                    float2 bv = *(const float2*)&bias[col];
                    *(float2*)&C[(size_t)row * N + col] =
                        make_float2(vx + bv.x, vy + bv.y);
                }
            }
        }
    }
}

// ---------------------------------------------------------------------------
// Masked linear attention, flash-style, FFMA2 inner loops.
// grid = (16 n-tiles, 48 bh). block = 256 threads, 64x64 output tile.
// Epilogue writes tf32-split output for the out-proj GEMM.
// ---------------------------------------------------------------------------
#define ATTN_SMEM ((4 * 64 * 68 + 64 * 64) * 4)

__global__ __launch_bounds__(256)
void attn_kernel(const float* __restrict__ mask)
{
    extern __shared__ float sm[];
    float* Qs = sm;                 // [64][68]  Qs[d][n]
    float* Ks = Qs + 64*68;         // [64][68]  Ks[d][m]
    float* Ms = Ks + 64*68;         // [64][68]  Ms[n][m]
    float* Ps = Ms + 64*68;         // [64][68]  Ps[m][n]
    float* Vs = Ps + 64*68;         // [64][64]  Vs[m][d]

    const int tid = threadIdx.x;
    const int tr  = tid >> 4;
    const int tc  = tid & 15;
    const int n0  = blockIdx.x * 64;
    const int bh  = blockIdx.y;
    const int qoff = bh * 64;

    #pragma unroll
    for (int i = 0; i < 4; i++) {
        const int l = tid + i * 256;
        const int n = l >> 4, d4 = (l & 15) * 4;
        float4 v = *(const float4*)&g_qk2[(size_t)(n0 + n) * QK_LD + qoff + d4];
        Qs[(d4+0)*68 + n] = v.x; Qs[(d4+1)*68 + n] = v.y;
        Qs[(d4+2)*68 + n] = v.z; Qs[(d4+3)*68 + n] = v.w;
    }

    u64 acc2[4][2];
    #pragma unroll
    for (int i = 0; i < 4; i++) { acc2[i][0] = 0ull; acc2[i][1] = 0ull; }
    float rs[4] = {};

    for (int mt = 0; mt < 16; mt++) {
        const int m0 = mt * 64;
        __syncthreads();

        #pragma unroll
        for (int i = 0; i < 4; i++) {
            const int l = tid + i * 256;
            const int r = l >> 4, c4 = (l & 15) * 4;
            float4 kv = *(const float4*)&g_qk2[(size_t)(m0 + r) * QK_LD + 3072 + qoff + c4];
            Ks[(c4+0)*68 + r] = kv.x; Ks[(c4+1)*68 + r] = kv.y;
            Ks[(c4+2)*68 + r] = kv.z; Ks[(c4+3)*68 + r] = kv.w;
            *(float4*)&Vs[r*64 + c4] =
                *(const float4*)&g_v[(size_t)(m0 + r) * V_LD + qoff + c4];
            *(float4*)&Ms[r*68 + c4] =
                *(const float4*)&mask[(size_t)(n0 + r) * 1024 + m0 + c4];
        }
        __syncthreads();

        u64 s2[4][2];
        #pragma unroll
        for (int i = 0; i < 4; i++) { s2[i][0] = 0ull; s2[i][1] = 0ull; }
        #pragma unroll 8
        for (int d = 0; d < 64; d++) {
            float4 q = *(const float4*)&Qs[d*68 + tr*4];
            u64 k0p = *(const u64*)&Ks[d*68 + tc*4];
            u64 k1p = *(const u64*)&Ks[d*68 + tc*4 + 2];
            const float qa[4] = {q.x, q.y, q.z, q.w};
            #pragma unroll
            for (int i = 0; i < 4; i++) {
                u64 qd; DUP2(qd, qa[i]);
                FFMA2(s2[i][0], qd, k0p);
                FFMA2(s2[i][1], qd, k1p);
            }
        }
        #pragma unroll
        for (int i = 0; i < 4; i++) {
            float s[4];
            UNPK2(s[0], s[1], s2[i][0]);
            UNPK2(s[2], s[3], s2[i][1]);
            #pragma unroll
            for (int j = 0; j < 4; j++)
                Ps[(tc*4+j)*68 + tr*4+i] = s[j] * Ms[(tr*4+i)*68 + tc*4+j];
        }
        __syncthreads();

        #pragma unroll 8
        for (int m = 0; m < 64; m++) {
            float4 p = *(const float4*)&Ps[m*68 + tr*4];
            u64 v0p = *(const u64*)&Vs[m*64 + tc*4];
            u64 v1p = *(const u64*)&Vs[m*64 + tc*4 + 2];
            const float pa[4] = {p.x, p.y, p.z, p.w};
            #pragma unroll
            for (int i = 0; i < 4; i++) {
                rs[i] += pa[i];
                u64 pd; DUP2(pd, pa[i]);
                FFMA2(acc2[i][0], pd, v0p);
                FFMA2(acc2[i][1], pd, v1p);
            }
        }
    }

    const int b = bh / 12, h = bh % 12;
    #pragma unroll
    for (int i = 0; i < 4; i++) {
        const float z = 1.f / (rs[i] + EPSF);
        float a[4];
        UNPK2(a[0], a[1], acc2[i][0]);
        UNPK2(a[2], a[3], acc2[i][1]);
        const size_t row = (size_t)(b * 1024 + n0 + tr*4 + i);
        float4 oh, ol;
        tf32_split(a[0]*z, oh.x, ol.x);
        tf32_split(a[1]*z, oh.y, ol.y);
        tf32_split(a[2]*z, oh.z, ol.z);
        tf32_split(a[3]*z, oh.w, ol.w);
        *(float4*)&g_ath[row * 768 + h*64 + tc*4] = oh;
        *(float4*)&g_atl[row * 768 + h*64 + tc*4] = ol;
    }
}

// ---------------------------------------------------------------------------

extern "C" void kernel_launch(void* const* d_in, const int* in_sizes, int n_in,
                              void* d_out, int out_size)
{
    (void)in_sizes; (void)n_in; (void)out_size;
    const float* x     = (const float*)d_in[0];   // [4,1024,768]
    const float* W_qkv = (const float*)d_in[1];   // [768,2304]
    const float* W_out = (const float*)d_in[2];   // [768,768]
    const float* b_out = (const float*)d_in[3];   // [768]
    const float* mask  = (const float*)d_in[4];   // [1024,1024]
    float* out = (float*)d_out;                   // [4,1024,768]

    float *p_xh, *p_xl, *p_wqh, *p_wql, *p_woh, *p_wol, *p_mh, *p_ml;
    float *p_qkh, *p_qkl, *p_qk2, *p_ath, *p_atl;
    cudaGetSymbolAddress((void**)&p_xh,  g_xh);
    cudaGetSymbolAddress((void**)&p_xl,  g_xl);
    cudaGetSymbolAddress((void**)&p_wqh, g_wqh);
    cudaGetSymbolAddress((void**)&p_wql, g_wql);
    cudaGetSymbolAddress((void**)&p_woh, g_woh);
    cudaGetSymbolAddress((void**)&p_wol, g_wol);
    cudaGetSymbolAddress((void**)&p_mh,  g_mh);
    cudaGetSymbolAddress((void**)&p_ml,  g_ml);
    cudaGetSymbolAddress((void**)&p_qkh, g_qkh);
    cudaGetSymbolAddress((void**)&p_qkl, g_qkl);
    cudaGetSymbolAddress((void**)&p_qk2, g_qk2);
    cudaGetSymbolAddress((void**)&p_ath, g_ath);
    cudaGetSymbolAddress((void**)&p_atl, g_atl);

    cudaFuncSetAttribute(attn_kernel,
                         cudaFuncAttributeMaxDynamicSharedMemorySize, ATTN_SMEM);
    cudaFuncSetAttribute(tgemm_kernel<false, 0>,
                         cudaFuncAttributeMaxDynamicSharedMemorySize, SMEM_NT);
    cudaFuncSetAttribute(tgemm_kernel<true, 1>,
                         cudaFuncAttributeMaxDynamicSharedMemorySize, SMEM_T);
    cudaFuncSetAttribute(tgemm_kernel<false, 2>,
                         cudaFuncAttributeMaxDynamicSharedMemorySize, SMEM_NT);

    dim3 blk(256);

    // 0) pre-split inputs (elementwise, bandwidth-bound, ~15us total)
    split_kernel<<<(4*NP*DIM/4 + 255)/256, 256>>>(x,     p_xh,  p_xl,  4*NP*DIM/4);
    split_kernel<<<(DIM*3*DIM/4 + 255)/256, 256>>>(W_qkv, p_wqh, p_wql, DIM*3*DIM/4);
    split_kernel<<<(DIM*DIM/4  + 255)/256, 256>>>(W_out, p_woh, p_wol, DIM*DIM/4);
    split_kernel<<<(NP*NP/4    + 255)/256, 256>>>(mask,  p_mh,  p_ml,  NP*NP/4);

    // 1) QKV GEMM: [4096,768] @ [768,2304] -> relu/eps + split scatter
    tgemm_kernel<false, 0><<<dim3(2304/128, 4096/128), blk, SMEM_NT>>>(
        p_xh, p_xl, p_wqh, p_wql, nullptr, nullptr, 4096, 2304, 768, 768, 2304);

    // 2) Graph mix: g_qk2 = (qk_hi+qk_lo) + 0.1 * (mask^T @ qk)
    tgemm_kernel<true, 1><<<dim3(6144/128, 1024/128), blk, SMEM_T>>>(
        p_mh, p_ml, p_qkh, p_qkl, p_qk2, nullptr, 1024, 6144, 1024, 1024, QK_LD);

    // 3) Masked linear attention -> g_ath/g_atl (split)
    attn_kernel<<<dim3(16, 48), blk, ATTN_SMEM>>>(mask);

    // 4) Output projection: [4096,768] @ [768,768] + b_out -> d_out
    tgemm_kernel<false, 2><<<dim3(768/128, 4096/128), blk, SMEM_NT>>>(
        p_ath, p_atl, p_woh, p_wol, out, b_out, 4096, 768, 768, 768, 768);
}

// round 14
// speedup vs baseline: 1.0644x; 1.0644x over previous
#include <cuda_runtime.h>
#include <cstdint>

#define EPSF 1e-6f

#define NP     1024
#define DIM    768
#define QK_LD  6144   /* q|k combined columns: 2 * 48 * 64 */
#define V_LD   3072

typedef unsigned long long u64;

// Packed f32x2 helpers (attention kernel)
#define FFMA2(d, a, b) \
    asm volatile("fma.rn.f32x2 %0, %1, %2, %0;" : "+l"(d) : "l"(a), "l"(b))
#define DUP2(d, s) \
    asm("mov.b64 %0, {%1, %1};" : "=l"(d) : "r"(__float_as_uint(s)))
#define UNPK2(lo, hi, d) \
    asm("mov.b64 {%0, %1}, %2;" : "=f"(lo), "=f"(hi) : "l"(d))

// tf32 split: x ~= hi + lo, both tf32-representable (3xTF32 trick)
__device__ __forceinline__ void tf32_split(float f, float& hi, float& lo) {
    uint32_t h, l;
    asm("cvt.rna.tf32.f32 %0, %1;" : "=r"(h) : "f"(f));
    float r = f - __uint_as_float(h);
    asm("cvt.rna.tf32.f32 %0, %1;" : "=r"(l) : "f"(r));
    hi = __uint_as_float(h);
    lo = __uint_as_float(l);
}

#define MMA_TF32(cc, a, b) \
    asm volatile("mma.sync.aligned.m16n8k8.row.col.f32.tf32.tf32.f32 " \
        "{%0,%1,%2,%3}, {%4,%5,%6,%7}, {%8,%9}, {%0,%1,%2,%3};" \
        : "+f"(cc[0]), "+f"(cc[1]), "+f"(cc[2]), "+f"(cc[3]) \
        : "r"(a[0]), "r"(a[1]), "r"(a[2]), "r"(a[3]), "r"(b[0]), "r"(b[1]))

// Scratch (device globals: allowed; no runtime allocation)
__device__ float g_qkbuf[NP * QK_LD];          // feature-mapped q|k, [n, col]
__device__ float g_qk2 [NP * QK_LD];           // q|k after graph mix
__device__ float g_v   [NP * V_LD];            // v, [n, col]
__device__ float g_attn[4 * NP * DIM];         // attention output [B*N, C]

// ---------------------------------------------------------------------------
// Tensor-core GEMM: 128x128 block tile, 16 warps (4m x 4n), warp tile 32x32,
// K-stage 16, mma.m16n8k8.tf32 with 3xTF32 split, 2-stage register pipeline.
// TRANSA=false: A row-major [M,K], smem [m][20].
// TRANSA=true:  op(A)=A^T with A [K,M], smem [k][136].
// EPI 0: qkv scatter+relu+eps   EPI 1: C = F + 0.1*acc   EPI 2: C = acc + bias
// ---------------------------------------------------------------------------
#define TS_B    2176                    /* 16*136 */
#define TS_A_NT 2560                    /* 128*20 */
#define STAGE_T   (4 * TS_B)            /* 8704 floats */
#define STAGE_NT  (2 * TS_A_NT + 2 * TS_B)  /* 9472 floats */
#define SMEM_T    (2 * STAGE_T  * 4)
#define SMEM_NT   (2 * STAGE_NT * 4)

template<bool TRANSA, int EPI>
__global__ __launch_bounds__(512, 1)
void tgemm_kernel(const float* __restrict__ A, const float* __restrict__ B,
                  float* __restrict__ C, const float* __restrict__ bias,
                  int M, int N, int K, int lda, int ldb)
{
    constexpr int AL_OFF = TRANSA ? TS_B : TS_A_NT;
    constexpr int BH_OFF = 2 * AL_OFF;
    constexpr int BL_OFF = BH_OFF + TS_B;
    constexpr int STAGE  = TRANSA ? STAGE_T : STAGE_NT;

    extern __shared__ float sm_[];

    const int tid  = threadIdx.x;
    const int lane = tid & 31;
    const int warp = tid >> 5;
    const int wm   = warp & 3;          // 0..3  (m)
    const int wn   = warp >> 2;         // 0..3  (n)
    const int g    = lane >> 2;         // 0..7
    const int tg   = lane & 3;          // 0..3
    const int m_base = blockIdx.y * 128;
    const int n_base = blockIdx.x * 128;

    // per-thread global load coordinates (fixed across k-tiles)
    const int a_r = TRANSA ? (tid >> 5) : (tid >> 2);       // row within tile
    const int a_c = TRANSA ? ((tid & 31) * 4) : ((tid & 3) * 4);
    const int b_k = tid >> 5;
    const int b_n = (tid & 31) * 4;

    float c[2][4][4];
    #pragma unroll
    for (int mt = 0; mt < 2; mt++)
        #pragma unroll
        for (int nt = 0; nt < 4; nt++)
            #pragma unroll
            for (int q = 0; q < 4; q++) c[mt][nt][q] = 0.f;

    float4 ra, rb;

    auto load_regs = [&](int k0) {
        const float* ap = TRANSA
            ? &A[(size_t)(k0 + a_r) * lda + m_base + a_c]
            : &A[(size_t)(m_base + a_r) * lda + k0 + a_c];
        ra = *(const float4*)ap;
        rb = *(const float4*)&B[(size_t)(k0 + b_k) * ldb + n_base + b_n];
    };

    auto store_stage = [&](float* base) {
        float* Ah = base;
        float* Al = base + AL_OFF;
        float* Bh = base + BH_OFF;
        float* Bl = base + BL_OFF;
        {
            float h[4], l[4];
            tf32_split(ra.x, h[0], l[0]);
            tf32_split(ra.y, h[1], l[1]);
            tf32_split(ra.z, h[2], l[2]);
            tf32_split(ra.w, h[3], l[3]);
            if (TRANSA) {
                *(float4*)&Ah[a_r * 136 + a_c] = make_float4(h[0], h[1], h[2], h[3]);
                *(float4*)&Al[a_r * 136 + a_c] = make_float4(l[0], l[1], l[2], l[3]);
            } else {
                *(float4*)&Ah[a_r * 20 + a_c] = make_float4(h[0], h[1], h[2], h[3]);
                *(float4*)&Al[a_r * 20 + a_c] = make_float4(l[0], l[1], l[2], l[3]);
            }
        }
        {
            float h[4], l[4];
            tf32_split(rb.x, h[0], l[0]);
            tf32_split(rb.y, h[1], l[1]);
            tf32_split(rb.z, h[2], l[2]);
            tf32_split(rb.w, h[3], l[3]);
            *(float4*)&Bh[b_k * 136 + b_n] = make_float4(h[0], h[1], h[2], h[3]);
            *(float4*)&Bl[b_k * 136 + b_n] = make_float4(l[0], l[1], l[2], l[3]);
        }
    };

    const int nk = K >> 4;

    // prologue: fill stage 0
    load_regs(0);
    store_stage(sm_);

    for (int kt = 0; kt < nk; kt++) {
        __syncthreads();                 // stage kt%2 ready; other stage free
        if (kt + 1 < nk)
            load_regs((kt + 1) << 4);    // global loads fly during MMA burst

        const float* base = sm_ + (kt & 1) * STAGE;
        const float* Ah = base;
        const float* Al = base + AL_OFF;
        const float* Bh = base + BH_OFF;
        const float* Bl = base + BL_OFF;

        #pragma unroll
        for (int ks = 0; ks < 16; ks += 8) {
            uint32_t bh[4][2], bl[4][2];
            #pragma unroll
            for (int nt = 0; nt < 4; nt++) {
                const int cb = wn * 32 + nt * 8 + g;
                bh[nt][0] = __float_as_uint(Bh[(ks + tg) * 136 + cb]);
                bh[nt][1] = __float_as_uint(Bh[(ks + tg + 4) * 136 + cb]);
                bl[nt][0] = __float_as_uint(Bl[(ks + tg) * 136 + cb]);
                bl[nt][1] = __float_as_uint(Bl[(ks + tg + 4) * 136 + cb]);
            }
            #pragma unroll
            for (int mt = 0; mt < 2; mt++) {
                const int rbv = wm * 32 + mt * 16;
                uint32_t ah[4], al[4];
                if (TRANSA) {
                    ah[0] = __float_as_uint(Ah[(ks + tg) * 136 + rbv + g]);
                    ah[1] = __float_as_uint(Ah[(ks + tg) * 136 + rbv + g + 8]);
                    ah[2] = __float_as_uint(Ah[(ks + tg + 4) * 136 + rbv + g]);
                    ah[3] = __float_as_uint(Ah[(ks + tg + 4) * 136 + rbv + g + 8]);
                    al[0] = __float_as_uint(Al[(ks + tg) * 136 + rbv + g]);
                    al[1] = __float_as_uint(Al[(ks + tg) * 136 + rbv + g + 8]);
                    al[2] = __float_as_uint(Al[(ks + tg + 4) * 136 + rbv + g]);
                    al[3] = __float_as_uint(Al[(ks + tg + 4) * 136 + rbv + g + 8]);
                } else {
                    ah[0] = __float_as_uint(Ah[(rbv + g) * 20 + ks + tg]);
                    ah[1] = __float_as_uint(Ah[(rbv + g + 8) * 20 + ks + tg]);
                    ah[2] = __float_as_uint(Ah[(rbv + g) * 20 + ks + tg + 4]);
                    ah[3] = __float_as_uint(Ah[(rbv + g + 8) * 20 + ks + tg + 4]);
                    al[0] = __float_as_uint(Al[(rbv + g) * 20 + ks + tg]);
                    al[1] = __float_as_uint(Al[(rbv + g + 8) * 20 + ks + tg]);
                    al[2] = __float_as_uint(Al[(rbv + g) * 20 + ks + tg + 4]);
                    al[3] = __float_as_uint(Al[(rbv + g + 8) * 20 + ks + tg + 4]);
                }
                #pragma unroll
                for (int nt = 0; nt < 4; nt++) {
                    MMA_TF32(c[mt][nt], ah, bh[nt]);   // hi*hi
                    MMA_TF32(c[mt][nt], ah, bl[nt]);   // hi*lo
                    MMA_TF32(c[mt][nt], al, bh[nt]);   // lo*hi
                }
            }
        }

        if (kt + 1 < nk)
            store_stage(sm_ + ((kt + 1) & 1) * STAGE);
    }

    // -------- epilogue (per-thread: rows r and r+8, col pair 2tg,2tg+1) -----
    #pragma unroll
    for (int mt = 0; mt < 2; mt++) {
        #pragma unroll
        for (int nt = 0; nt < 4; nt++) {
            const int row0 = m_base + wm * 32 + mt * 16 + g;
            const int col  = n_base + wn * 32 + nt * 8 + 2 * tg;
            #pragma unroll
            for (int h2 = 0; h2 < 2; h2++) {
                const int row = row0 + h2 * 8;
                float vx = c[mt][nt][h2 * 2 + 0];
                float vy = c[mt][nt][h2 * 2 + 1];
                if (EPI == 0) {
                    const int bb = row >> 10;
                    const int n  = row & 1023;
                    if (col < 1536) {
                        vx = fmaxf(vx, 0.f) + EPSF;
                        vy = fmaxf(vy, 0.f) + EPSF;
                        const int off = (col < 768) ? (bb * 768 + col)
                                                    : (3072 + bb * 768 + (col - 768));
                        *(float2*)&g_qkbuf[(size_t)n * QK_LD + off] = make_float2(vx, vy);
                    } else {
                        *(float2*)&g_v[(size_t)n * V_LD + bb * 768 + (col - 1536)] =
                            make_float2(vx, vy);
                    }
                } else if (EPI == 1) {
                    float2 f = *(const float2*)&g_qkbuf[(size_t)row * N + col];
                    *(float2*)&C[(size_t)row * N + col] =
                        make_float2(f.x + 0.1f * vx, f.y + 0.1f * vy);
                } else {
                    float2 bv = *(const float2*)&bias[col];
                    *(float2*)&C[(size_t)row * N + col] =
                        make_float2(vx + bv.x, vy + bv.y);
                }
            }
        }
    }
}

// ---------------------------------------------------------------------------
// Masked linear attention, flash-style, FFMA2 inner loops (unchanged, passing).
// grid = (16 n-tiles, 48 bh). block = 256 threads, 64x64 output tile.
// ---------------------------------------------------------------------------
#define ATTN_SMEM ((4 * 64 * 68 + 64 * 64) * 4)

__global__ __launch_bounds__(256)
void attn_kernel(const float* __restrict__ mask)
{
    extern __shared__ float sm[];
    float* Qs = sm;                 // [64][68]  Qs[d][n]
    float* Ks = Qs + 64*68;         // [64][68]  Ks[d][m]
    float* Ms = Ks + 64*68;         // [64][68]  Ms[n][m]
    float* Ps = Ms + 64*68;         // [64][68]  Ps[m][n]
    float* Vs = Ps + 64*68;         // [64][64]  Vs[m][d]

    const int tid = threadIdx.x;
    const int tr  = tid >> 4;
    const int tc  = tid & 15;
    const int n0  = blockIdx.x * 64;
    const int bh  = blockIdx.y;
    const int qoff = bh * 64;

    #pragma unroll
    for (int i = 0; i < 4; i++) {
        const int l = tid + i * 256;
        const int n = l >> 4, d4 = (l & 15) * 4;
        float4 v = *(const float4*)&g_qk2[(size_t)(n0 + n) * QK_LD + qoff + d4];
        Qs[(d4+0)*68 + n] = v.x; Qs[(d4+1)*68 + n] = v.y;
        Qs[(d4+2)*68 + n] = v.z; Qs[(d4+3)*68 + n] = v.w;
    }

    u64 acc2[4][2];
    #pragma unroll
    for (int i = 0; i < 4; i++) { acc2[i][0] = 0ull; acc2[i][1] = 0ull; }
    float rs[4] = {};

    for (int mt = 0; mt < 16; mt++) {
        const int m0 = mt * 64;
        __syncthreads();

        #pragma unroll
        for (int i = 0; i < 4; i++) {
            const int l = tid + i * 256;
            const int r = l >> 4, c4 = (l & 15) * 4;
            float4 kv = *(const float4*)&g_qk2[(size_t)(m0 + r) * QK_LD + 3072 + qoff + c4];
            Ks[(c4+0)*68 + r] = kv.x; Ks[(c4+1)*68 + r] = kv.y;
            Ks[(c4+2)*68 + r] = kv.z; Ks[(c4+3)*68 + r] = kv.w;
            *(float4*)&Vs[r*64 + c4] =
                *(const float4*)&g_v[(size_t)(m0 + r) * V_LD + qoff + c4];
            *(float4*)&Ms[r*68 + c4] =
                *(const float4*)&mask[(size_t)(n0 + r) * 1024 + m0 + c4];
        }
        __syncthreads();

        u64 s2[4][2];
        #pragma unroll
        for (int i = 0; i < 4; i++) { s2[i][0] = 0ull; s2[i][1] = 0ull; }
        #pragma unroll 8
        for (int d = 0; d < 64; d++) {
            float4 q = *(const float4*)&Qs[d*68 + tr*4];
            u64 k0p = *(const u64*)&Ks[d*68 + tc*4];
            u64 k1p = *(const u64*)&Ks[d*68 + tc*4 + 2];
            const float qa[4] = {q.x, q.y, q.z, q.w};
            #pragma unroll
            for (int i = 0; i < 4; i++) {
                u64 qd; DUP2(qd, qa[i]);
                FFMA2(s2[i][0], qd, k0p);
                FFMA2(s2[i][1], qd, k1p);
            }
        }
        #pragma unroll
        for (int i = 0; i < 4; i++) {
            float s[4];
            UNPK2(s[0], s[1], s2[i][0]);
            UNPK2(s[2], s[3], s2[i][1]);
            #pragma unroll
            for (int j = 0; j < 4; j++)
                Ps[(tc*4+j)*68 + tr*4+i] = s[j] * Ms[(tr*4+i)*68 + tc*4+j];
        }
        __syncthreads();

        #pragma unroll 8
        for (int m = 0; m < 64; m++) {
            float4 p = *(const float4*)&Ps[m*68 + tr*4];
            u64 v0p = *(const u64*)&Vs[m*64 + tc*4];
            u64 v1p = *(const u64*)&Vs[m*64 + tc*4 + 2];
            const float pa[4] = {p.x, p.y, p.z, p.w};
            #pragma unroll
            for (int i = 0; i < 4; i++) {
                rs[i] += pa[i];
                u64 pd; DUP2(pd, pa[i]);
                FFMA2(acc2[i][0], pd, v0p);
                FFMA2(acc2[i][1], pd, v1p);
            }
        }
    }

    const int b = bh / 12, h = bh % 12;
    #pragma unroll
    for (int i = 0; i < 4; i++) {
        const float z = 1.f / (rs[i] + EPSF);
        float a[4];
        UNPK2(a[0], a[1], acc2[i][0]);
        UNPK2(a[2], a[3], acc2[i][1]);
        const size_t row = (size_t)(b * 1024 + n0 + tr*4 + i);
        float4 o = make_float4(a[0]*z, a[1]*z, a[2]*z, a[3]*z);
        *(float4*)&g_attn[row * 768 + h*64 + tc*4] = o;
    }
}

// ---------------------------------------------------------------------------

extern "C" void kernel_launch(void* const* d_in, const int* in_sizes, int n_in,
                              void* d_out, int out_size)
{
    (void)in_sizes; (void)n_in; (void)out_size;
    const float* x     = (const float*)d_in[0];   // [4,1024,768]
    const float* W_qkv = (const float*)d_in[1];   // [768,2304]
    const float* W_out = (const float*)d_in[2];   // [768,768]
    const float* b_out = (const float*)d_in[3];   // [768]
    const float* mask  = (const float*)d_in[4];   // [1024,1024]
    float* out = (float*)d_out;                   // [4,1024,768]

    float *p_qkbuf = nullptr, *p_qk2 = nullptr, *p_attn = nullptr;
    cudaGetSymbolAddress((void**)&p_qkbuf, g_qkbuf);
    cudaGetSymbolAddress((void**)&p_qk2,  g_qk2);
    cudaGetSymbolAddress((void**)&p_attn, g_attn);

    cudaFuncSetAttribute(attn_kernel,
                         cudaFuncAttributeMaxDynamicSharedMemorySize, ATTN_SMEM);
    cudaFuncSetAttribute(tgemm_kernel<false, 0>,
                         cudaFuncAttributeMaxDynamicSharedMemorySize, SMEM_NT);
    cudaFuncSetAttribute(tgemm_kernel<true, 1>,
                         cudaFuncAttributeMaxDynamicSharedMemorySize, SMEM_T);
    cudaFuncSetAttribute(tgemm_kernel<false, 2>,
                         cudaFuncAttributeMaxDynamicSharedMemorySize, SMEM_NT);

    dim3 blk(512);

    // 1) QKV GEMM: [4096,768] @ [768,2304] -> relu/eps scatter into g_qkbuf / g_v
    tgemm_kernel<false, 0><<<dim3(2304/128, 4096/128), blk, SMEM_NT>>>(
        x, W_qkv, nullptr, nullptr, 4096, 2304, 768, 768, 2304);

    // 2) Graph mix: g_qk2 = F + 0.1 * (mask^T @ F), F = g_qkbuf [1024,6144]
    tgemm_kernel<true, 1><<<dim3(6144/128, 1024/128), blk, SMEM_T>>>(
        mask, p_qkbuf, p_qk2, nullptr, 1024, 6144, 1024, 1024, QK_LD);

    // 3) Masked linear attention -> g_attn [4096,768]
    attn_kernel<<<dim3(16, 48), dim3(256), ATTN_SMEM>>>(mask);

    // 4) Output projection: [4096,768] @ [768,768] + b_out -> d_out
    tgemm_kernel<false, 2><<<dim3(768/128, 4096/128), blk, SMEM_NT>>>(
        p_attn, W_out, out, b_out, 4096, 768, 768, 768, 768);
}